// round 13
// baseline (speedup 1.0000x reference)
#include <cuda_runtime.h>
#include <float.h>

#define BB 4
#define NR 180
#define CC 512
#define HH 48
#define WW 48
#define HW (HH*WW)
#define F_IN 2048
#define OO 64
#define EPSV 1e-5f
#define C4 (CC/4)          // 128 float4 per (h,w)
#define LVLSZ (BB*HH*WW*CC)
#define MT 12              // ROIs per gemm block
#define KS 16              // gemm k-split
#define KQ (F_IN/KS)       // 128
#define NBUILD (BB*WW*(CC/128))   // 768 column-scan blocks

// ---------------- device scratch ----------------
__device__ float d_feat_t[LVLSZ];               // [B,H,W,C] level pw=1 (transposed)
__device__ float d_lvl[2 * LVLSZ];              // levels pw=4, pw=12
__device__ float d_pooled[BB * NR * F_IN];      // relu'd pooled
__device__ float d_W1t[F_IN * OO];              // W1 transposed [F,O]
__device__ float d_Wsum[OO];                    // sum_f W1[o,f]
__device__ float d_s1[NR];                      // per-n sum over (b,f)
__device__ float d_s2[NR];                      // per-n sumsq
__device__ float d_g16[KS][BB * NR * OO];       // GEMM k-slice partials

__device__ __forceinline__ void max4(float4& a, const float4& b) {
    a.x = fmaxf(a.x, b.x); a.y = fmaxf(a.y, b.y);
    a.z = fmaxf(a.z, b.z); a.w = fmaxf(a.w, b.w);
}

// ---------------- K1: features [B,C,HW] -> [B,HW,C], tiled, coalesced ----------
__global__ void k_transpose(const float* __restrict__ feat) {
    __shared__ float tile[32][33];
    int b = blockIdx.z;
    int c0 = blockIdx.y * 32;
    int p0 = blockIdx.x * 32;       // HW=2304 divisible by 32
    #pragma unroll
    for (int k = 0; k < 32; k += 8) {
        int c = c0 + threadIdx.y + k;
        tile[threadIdx.y + k][threadIdx.x] =
            feat[((size_t)(b * CC + c)) * HW + p0 + threadIdx.x];
    }
    __syncthreads();
    #pragma unroll
    for (int k = 0; k < 32; k += 8) {
        int p = p0 + threadIdx.y + k;
        d_feat_t[((size_t)b * HW + p) * CC + c0 + threadIdx.x] =
            tile[threadIdx.x][threadIdx.y + k];
    }
}

// ---------------- K2: column-scan sparse-table build (coalesced) + W1 prep ------
__global__ void __launch_bounds__(128) k_build4(const float* __restrict__ W1) {
    int blk = blockIdx.x;
    int tid = threadIdx.x;

    if (blk >= NBUILD) {
        int o = blk - NBUILD;                   // 0..63
        if (o == 0) {
            for (int i = tid; i < NR; i += 128) { d_s1[i] = 0.f; d_s2[i] = 0.f; }
        }
        __shared__ float red[128];
        float s = 0.f;
        for (int f = tid; f < F_IN; f += 128) {
            float v = W1[o * F_IN + f];
            d_W1t[f * OO + o] = v;
            s += v;
        }
        red[tid] = s;
        __syncthreads();
        for (int st = 64; st > 0; st >>= 1) {
            if (tid < st) red[tid] += red[tid + st];
            __syncthreads();
        }
        if (tid == 0) d_Wsum[o] = red[0];
        return;
    }

    int bw = blk >> 2;                  // (b,w)
    int cp = blk & 3;                   // channel part
    int b = bw / WW, w = bw % WW;
    int c = cp * 128 + tid;

    size_t base = ((size_t)(b * HH) * WW + w) * CC + c;
    const size_t HS = (size_t)WW * CC;  // h stride

    float v[HH];
    #pragma unroll
    for (int h = 0; h < HH; h++) v[h] = d_feat_t[base + h * HS];

    // pw1 -> pw4: passes d=1 then d=2
    #pragma unroll
    for (int h = 0; h < HH - 1; h++) v[h] = fmaxf(v[h], v[h + 1]);
    #pragma unroll
    for (int h = 0; h < HH - 2; h++) v[h] = fmaxf(v[h], v[h + 2]);
    #pragma unroll
    for (int h = 0; h < HH; h++) d_lvl[base + h * HS] = v[h];           // pw4

    // pw4 -> pw12: two d=4 passes
    #pragma unroll
    for (int h = 0; h < HH - 4; h++) v[h] = fmaxf(v[h], v[h + 4]);
    #pragma unroll
    for (int h = 0; h < HH - 8; h++) v[h] = fmaxf(v[h], v[h + 4]);
    #pragma unroll
    for (int h = 0; h < HH; h++) d_lvl[LVLSZ + base + h * HS] = v[h];   // pw12
}

// ---------------- K3: ROI pool via range-max lookups + ReLU + BN1 stats --------
__global__ void __launch_bounds__(256) k_roipool(const float* __restrict__ rois) {
    int bn = blockIdx.x;
    int b = bn / NR;
    const float* r = rois + bn * 4;
    int r0 = (int)truncf(r[0] * 0.25f), r1 = (int)truncf(r[1] * 0.25f);
    int r2 = (int)ceilf(r[2] * 0.25f),  r3 = (int)ceilf(r[3] * 0.25f);
    int hs = r2 - r0 + 1, ws = r3 - r1 + 1;
    int lenh = (hs + 1) >> 1;
    int lenw = (ws + 1) >> 1;
    int sh1 = r0 + (hs >> 1);
    int sw1 = r1 + (ws >> 1);

    const float* Lf;
    int pw;
    if (lenh >= 12)     { pw = 12; Lf = d_lvl + (size_t)LVLSZ; }
    else if (lenh >= 4) { pw = 4;  Lf = d_lvl; }
    else                { pw = 1;  Lf = d_feat_t; }
    int nlk = (lenh + pw - 1) / pw;       // 1..3
    const float4* L4 = (const float4*)Lf;

    int tid = threadIdx.x;
    int cq = tid & 127;
    int half = tid >> 7;
    int wstart = half ? sw1 : r1;
    size_t rb = (size_t)(b * HH) * WW;

    const float4 NEG = make_float4(-FLT_MAX, -FLT_MAX, -FLT_MAX, -FLT_MAX);
    float4 m0 = NEG, m1 = NEG;
    int cap = lenh - pw;
    for (int j = 0; j < nlk; j++) {
        int ho = j * pw; if (ho > cap) ho = cap;
        const float4* pA = L4 + (rb + (size_t)(r0  + ho) * WW + wstart) * C4 + cq;
        const float4* pB = L4 + (rb + (size_t)(sh1 + ho) * WW + wstart) * C4 + cq;
        #pragma unroll 2
        for (int w = lenw; w > 0; --w) {
            float4 va = *pA, vb = *pB;
            pA += C4; pB += C4;
            max4(m0, va); max4(m1, vb);
        }
    }

    __shared__ float4 sm0[128], sm1[128];
    __shared__ float rs[128], rq[128];
    if (half == 1) { sm0[cq] = m0; sm1[cq] = m1; }
    __syncthreads();
    if (half == 0) {
        const float4 Z = make_float4(0.f, 0.f, 0.f, 0.f);
        float4 m00 = m0, m10 = m1, m01 = sm0[cq], m11 = sm1[cq];
        max4(m00, Z); max4(m01, Z); max4(m10, Z); max4(m11, Z);
        float4 o0 = make_float4(m00.x, m01.x, m10.x, m11.x);
        float4 o1 = make_float4(m00.y, m01.y, m10.y, m11.y);
        float4 o2 = make_float4(m00.z, m01.z, m10.z, m11.z);
        float4 o3 = make_float4(m00.w, m01.w, m10.w, m11.w);
        float4* out = (float4*)(d_pooled + (size_t)bn * F_IN + cq * 16);
        out[0] = o0; out[1] = o1; out[2] = o2; out[3] = o3;
        float s = (o0.x + o0.y + o0.z + o0.w) + (o1.x + o1.y + o1.z + o1.w)
                + (o2.x + o2.y + o2.z + o2.w) + (o3.x + o3.y + o3.z + o3.w);
        float q = o0.x*o0.x + o0.y*o0.y + o0.z*o0.z + o0.w*o0.w
                + o1.x*o1.x + o1.y*o1.y + o1.z*o1.z + o1.w*o1.w
                + o2.x*o2.x + o2.y*o2.y + o2.z*o2.z + o2.w*o2.w
                + o3.x*o3.x + o3.y*o3.y + o3.z*o3.z + o3.w*o3.w;
        rs[cq] = s; rq[cq] = q;
    }
    __syncthreads();
    for (int st = 64; st > 0; st >>= 1) {
        if (tid < st) { rs[tid] += rs[tid + st]; rq[tid] += rq[tid + st]; }
        __syncthreads();
    }
    if (tid == 0) {
        int n = bn % NR;
        atomicAdd(&d_s1[n], rs[0]);
        atomicAdd(&d_s2[n], rq[0]);
    }
}

// ---------------- K4: GEMM v7 — v6 layout + W register double-buffer ------------
__global__ void __launch_bounds__(256) k_gemm() {
    __shared__ float xs[MT][KQ];             // 6KB
    __shared__ float part[4][MT][OO];        // 12KB
    int mb = blockIdx.x;                     // 0..59
    int ks = blockIdx.y;                     // 0..15
    int b = mb / (NR / MT);
    int n0 = (mb % (NR / MT)) * MT;
    int tid = threadIdx.x;

    const float4* P4 = (const float4*)d_pooled;
    for (int i4 = tid; i4 < MT * (KQ / 4); i4 += 256) {
        int nl = i4 >> 5, k4 = i4 & 31;
        float4 v = P4[((size_t)(b * NR + n0 + nl)) * (F_IN / 4) + ks * (KQ / 4) + k4];
        *(float4*)&xs[nl][k4 * 4] = v;
    }
    __syncthreads();

    int o = tid & 63;
    int q = tid >> 6;                        // 0..3, covers 32 k (uniform per warp)
    float acc[MT] = {};
    const float* Wp = d_W1t + (size_t)(ks * KQ + q * 32) * OO + o;
    float w0 = Wp[0 * OO], w1 = Wp[1 * OO], w2 = Wp[2 * OO], w3 = Wp[3 * OO];
    #pragma unroll
    for (int k = 0; k < 32; k += 4) {
        float nw0 = 0.f, nw1 = 0.f, nw2 = 0.f, nw3 = 0.f;
        if (k + 4 < 32) {                    // prefetch next W quad
            nw0 = Wp[(k + 4) * OO];
            nw1 = Wp[(k + 5) * OO];
            nw2 = Wp[(k + 6) * OO];
            nw3 = Wp[(k + 7) * OO];
        }
        #pragma unroll
        for (int nl = 0; nl < MT; nl++) {
            float4 x = *(const float4*)&xs[nl][q * 32 + k];
            acc[nl] = fmaf(x.x, w0, acc[nl]);
            acc[nl] = fmaf(x.y, w1, acc[nl]);
            acc[nl] = fmaf(x.z, w2, acc[nl]);
            acc[nl] = fmaf(x.w, w3, acc[nl]);
        }
        w0 = nw0; w1 = nw1; w2 = nw2; w3 = nw3;
    }
    #pragma unroll
    for (int nl = 0; nl < MT; nl++)
        part[q][nl][o] = acc[nl];
    __syncthreads();

    for (int i = tid; i < MT * OO; i += 256) {
        int nl = i >> 6, oo = i & 63;
        float g = part[0][nl][oo] + part[1][nl][oo]
                + part[2][nl][oo] + part[3][nl][oo];
        d_g16[ks][((size_t)(b * NR + n0 + nl)) * OO + oo] = g;
    }
}

// ---------------- K5: finalize — 512 threads, split ks-sum -------------------
__global__ void __launch_bounds__(512) k_final(const float* __restrict__ gamma1,
                        const float* __restrict__ beta1,
                        const float* __restrict__ bl1,
                        const float* __restrict__ gamma2,
                        const float* __restrict__ beta2,
                        float* __restrict__ out) {
    int n = blockIdx.x;
    int t = threadIdx.x;                 // 0..511
    int hh = t >> 8;                     // ks-half
    int t2 = t & 255;
    int b = t2 >> 6, o = t2 & 63;

    size_t gi = ((size_t)(b * NR + n)) * OO + o;
    float gpart = 0.f;
    #pragma unroll
    for (int ks = 0; ks < KS / 2; ks++) gpart += d_g16[hh * (KS / 2) + ks][gi];

    __shared__ float gsh[256];
    __shared__ float rs[256], rq[256];
    if (hh == 1) gsh[t2] = gpart;
    __syncthreads();

    float y = 0.f;
    if (hh == 0) {
        const float inv1 = 1.0f / (BB * F_IN);
        float mean1 = d_s1[n] * inv1;
        float var1 = d_s2[n] * inv1 - mean1 * mean1;
        float a1 = gamma1[n] * rsqrtf(var1 + EPSV);
        float c1 = beta1[n] - a1 * mean1;
        y = a1 * (gpart + gsh[t2]) + c1 * d_Wsum[o] + bl1[o];
        rs[t2] = y;
        rq[t2] = y * y;
    }
    __syncthreads();
    for (int st = 128; st > 0; st >>= 1) {
        if (t < st) { rs[t] += rs[t + st]; rq[t] += rq[t + st]; }
        __syncthreads();
    }
    if (hh == 0) {
        float mean = rs[0] * (1.0f / 256.0f);
        float var = rq[0] * (1.0f / 256.0f) - mean * mean;
        out[gi] = (y - mean) * rsqrtf(var + EPSV) * gamma2[n] + beta2[n];
    }
}

// ---------------- launch ----------------
extern "C" void kernel_launch(void* const* d_in, const int* in_sizes, int n_in,
                              void* d_out, int out_size) {
    const float* features = (const float*)d_in[0];
    const float* rois     = (const float*)d_in[1];
    const float* gamma1   = (const float*)d_in[2];
    const float* beta1    = (const float*)d_in[3];
    const float* W1       = (const float*)d_in[4];
    const float* bl1      = (const float*)d_in[5];
    const float* gamma2   = (const float*)d_in[6];
    const float* beta2    = (const float*)d_in[7];
    float* out = (float*)d_out;

    dim3 tgrid(HW / 32, CC / 32, BB);
    k_transpose<<<tgrid, dim3(32, 8)>>>(features);
    k_build4<<<NBUILD + OO, 128>>>(W1);
    k_roipool<<<BB * NR, 256>>>(rois);
    dim3 ggrid(BB * (NR / MT), KS);
    k_gemm<<<ggrid, 256>>>();
    k_final<<<NR, 512>>>(gamma1, beta1, bl1, gamma2, beta2, out);
}

// round 14
// speedup vs baseline: 1.0143x; 1.0143x over previous
#include <cuda_runtime.h>
#include <float.h>

#define BB 4
#define NR 180
#define CC 512
#define HH 48
#define WW 48
#define HW (HH*WW)
#define F_IN 2048
#define OO 64
#define EPSV 1e-5f
#define C4 (CC/4)          // 128 float4 per (h,w)
#define LVLSZ (BB*HH*WW*CC)
#define MT 12              // ROIs per gemm block
#define KS 16              // gemm k-split
#define KQ (F_IN/KS)       // 128
#define NBUILD (BB*WW*(CC/128))   // 768 column-scan blocks

// ---------------- device scratch ----------------
__device__ float d_feat_t[LVLSZ];               // [B,H,W,C] level pw=1 (transposed)
__device__ float d_lvl[2 * LVLSZ];              // levels pw=4, pw=12
__device__ float d_pooled[BB * NR * F_IN];      // relu'd pooled
__device__ float d_W1t[F_IN * OO];              // W1 transposed [F,O]
__device__ float d_Wsum[OO];                    // sum_f W1[o,f]
__device__ float d_s1[NR];                      // per-n sum over (b,f)
__device__ float d_s2[NR];                      // per-n sumsq
__device__ float d_g16[KS][BB * NR * OO];       // GEMM k-slice partials

__device__ __forceinline__ void max4(float4& a, const float4& b) {
    a.x = fmaxf(a.x, b.x); a.y = fmaxf(a.y, b.y);
    a.z = fmaxf(a.z, b.z); a.w = fmaxf(a.w, b.w);
}

// packed dual-fp32 FMA: d = a*b + d  (lo,hi lanes independent)
__device__ __forceinline__ void ffma2(unsigned long long& d,
                                      unsigned long long a,
                                      unsigned long long b) {
    asm("fma.rn.f32x2 %0, %1, %2, %0;" : "+l"(d) : "l"(a), "l"(b));
}
__device__ __forceinline__ unsigned long long packww(float w) {
    unsigned long long r;
    asm("mov.b64 %0, {%1, %1};" : "=l"(r) : "f"(w));
    return r;
}

// ---------------- K1: features [B,C,HW] -> [B,HW,C], tiled, coalesced ----------
__global__ void k_transpose(const float* __restrict__ feat) {
    __shared__ float tile[32][33];
    int b = blockIdx.z;
    int c0 = blockIdx.y * 32;
    int p0 = blockIdx.x * 32;       // HW=2304 divisible by 32
    #pragma unroll
    for (int k = 0; k < 32; k += 8) {
        int c = c0 + threadIdx.y + k;
        tile[threadIdx.y + k][threadIdx.x] =
            feat[((size_t)(b * CC + c)) * HW + p0 + threadIdx.x];
    }
    __syncthreads();
    #pragma unroll
    for (int k = 0; k < 32; k += 8) {
        int p = p0 + threadIdx.y + k;
        d_feat_t[((size_t)b * HW + p) * CC + c0 + threadIdx.x] =
            tile[threadIdx.x][threadIdx.y + k];
    }
}

// ---------------- K2: column-scan sparse-table build (coalesced) + W1 prep ------
__global__ void __launch_bounds__(128) k_build4(const float* __restrict__ W1) {
    int blk = blockIdx.x;
    int tid = threadIdx.x;

    if (blk >= NBUILD) {
        int o = blk - NBUILD;                   // 0..63
        if (o == 0) {
            for (int i = tid; i < NR; i += 128) { d_s1[i] = 0.f; d_s2[i] = 0.f; }
        }
        __shared__ float red[128];
        float s = 0.f;
        for (int f = tid; f < F_IN; f += 128) {
            float v = W1[o * F_IN + f];
            d_W1t[f * OO + o] = v;
            s += v;
        }
        red[tid] = s;
        __syncthreads();
        for (int st = 64; st > 0; st >>= 1) {
            if (tid < st) red[tid] += red[tid + st];
            __syncthreads();
        }
        if (tid == 0) d_Wsum[o] = red[0];
        return;
    }

    int bw = blk >> 2;                  // (b,w)
    int cp = blk & 3;                   // channel part
    int b = bw / WW, w = bw % WW;
    int c = cp * 128 + tid;

    size_t base = ((size_t)(b * HH) * WW + w) * CC + c;
    const size_t HS = (size_t)WW * CC;  // h stride

    float v[HH];
    #pragma unroll
    for (int h = 0; h < HH; h++) v[h] = d_feat_t[base + h * HS];

    // pw1 -> pw4: passes d=1 then d=2
    #pragma unroll
    for (int h = 0; h < HH - 1; h++) v[h] = fmaxf(v[h], v[h + 1]);
    #pragma unroll
    for (int h = 0; h < HH - 2; h++) v[h] = fmaxf(v[h], v[h + 2]);
    #pragma unroll
    for (int h = 0; h < HH; h++) d_lvl[base + h * HS] = v[h];           // pw4

    // pw4 -> pw12: two d=4 passes
    #pragma unroll
    for (int h = 0; h < HH - 4; h++) v[h] = fmaxf(v[h], v[h + 4]);
    #pragma unroll
    for (int h = 0; h < HH - 8; h++) v[h] = fmaxf(v[h], v[h + 4]);
    #pragma unroll
    for (int h = 0; h < HH; h++) d_lvl[LVLSZ + base + h * HS] = v[h];   // pw12
}

// ---------------- K3: ROI pool via range-max lookups + ReLU + BN1 stats --------
__global__ void __launch_bounds__(256) k_roipool(const float* __restrict__ rois) {
    int bn = blockIdx.x;
    int b = bn / NR;
    const float* r = rois + bn * 4;
    int r0 = (int)truncf(r[0] * 0.25f), r1 = (int)truncf(r[1] * 0.25f);
    int r2 = (int)ceilf(r[2] * 0.25f),  r3 = (int)ceilf(r[3] * 0.25f);
    int hs = r2 - r0 + 1, ws = r3 - r1 + 1;
    int lenh = (hs + 1) >> 1;
    int lenw = (ws + 1) >> 1;
    int sh1 = r0 + (hs >> 1);
    int sw1 = r1 + (ws >> 1);

    const float* Lf;
    int pw;
    if (lenh >= 12)     { pw = 12; Lf = d_lvl + (size_t)LVLSZ; }
    else if (lenh >= 4) { pw = 4;  Lf = d_lvl; }
    else                { pw = 1;  Lf = d_feat_t; }
    int nlk = (lenh + pw - 1) / pw;       // 1..3
    const float4* L4 = (const float4*)Lf;

    int tid = threadIdx.x;
    int cq = tid & 127;
    int half = tid >> 7;
    int wstart = half ? sw1 : r1;
    size_t rb = (size_t)(b * HH) * WW;

    const float4 NEG = make_float4(-FLT_MAX, -FLT_MAX, -FLT_MAX, -FLT_MAX);
    float4 m0 = NEG, m1 = NEG;
    int cap = lenh - pw;
    for (int j = 0; j < nlk; j++) {
        int ho = j * pw; if (ho > cap) ho = cap;
        const float4* pA = L4 + (rb + (size_t)(r0  + ho) * WW + wstart) * C4 + cq;
        const float4* pB = L4 + (rb + (size_t)(sh1 + ho) * WW + wstart) * C4 + cq;
        #pragma unroll 2
        for (int w = lenw; w > 0; --w) {
            float4 va = *pA, vb = *pB;
            pA += C4; pB += C4;
            max4(m0, va); max4(m1, vb);
        }
    }

    __shared__ float4 sm0[128], sm1[128];
    __shared__ float rs[128], rq[128];
    if (half == 1) { sm0[cq] = m0; sm1[cq] = m1; }
    __syncthreads();
    if (half == 0) {
        const float4 Z = make_float4(0.f, 0.f, 0.f, 0.f);
        float4 m00 = m0, m10 = m1, m01 = sm0[cq], m11 = sm1[cq];
        max4(m00, Z); max4(m01, Z); max4(m10, Z); max4(m11, Z);
        float4 o0 = make_float4(m00.x, m01.x, m10.x, m11.x);
        float4 o1 = make_float4(m00.y, m01.y, m10.y, m11.y);
        float4 o2 = make_float4(m00.z, m01.z, m10.z, m11.z);
        float4 o3 = make_float4(m00.w, m01.w, m10.w, m11.w);
        float4* out = (float4*)(d_pooled + (size_t)bn * F_IN + cq * 16);
        out[0] = o0; out[1] = o1; out[2] = o2; out[3] = o3;
        float s = (o0.x + o0.y + o0.z + o0.w) + (o1.x + o1.y + o1.z + o1.w)
                + (o2.x + o2.y + o2.z + o2.w) + (o3.x + o3.y + o3.z + o3.w);
        float q = o0.x*o0.x + o0.y*o0.y + o0.z*o0.z + o0.w*o0.w
                + o1.x*o1.x + o1.y*o1.y + o1.z*o1.z + o1.w*o1.w
                + o2.x*o2.x + o2.y*o2.y + o2.z*o2.z + o2.w*o2.w
                + o3.x*o3.x + o3.y*o3.y + o3.z*o3.z + o3.w*o3.w;
        rs[cq] = s; rq[cq] = q;
    }
    __syncthreads();
    for (int st = 64; st > 0; st >>= 1) {
        if (tid < st) { rs[tid] += rs[tid + st]; rq[tid] += rq[tid + st]; }
        __syncthreads();
    }
    if (tid == 0) {
        int n = bn % NR;
        atomicAdd(&d_s1[n], rs[0]);
        atomicAdd(&d_s2[n], rq[0]);
    }
}

// ---------------- K4: GEMM v8 — smem-staged W + packed f32x2 FMA ----------------
// 256 threads = 64 o x 4 k-groups(32k). acc = 6 packed ROI-pairs.
__global__ void __launch_bounds__(256) k_gemm() {
    __shared__ float Ws[KQ][OO];             // 32KB
    __shared__ float2 xp[MT / 2][KQ];        // 6KB, xp[p][k] = (x[2p][k], x[2p+1][k])
    __shared__ float part[4][MT][OO];        // 12KB
    int mb = blockIdx.x;                     // 0..59
    int ks = blockIdx.y;                     // 0..15
    int b = mb / (NR / MT);
    int n0 = (mb % (NR / MT)) * MT;
    int tid = threadIdx.x;

    // stage W slice [KQ][OO] coalesced
    {
        const float4* W4 = (const float4*)(d_W1t + (size_t)ks * KQ * OO);
        float4* S4 = (float4*)Ws;
        #pragma unroll
        for (int j = 0; j < (KQ * OO / 4) / 256; j++)   // 8 iters
            S4[tid + j * 256] = W4[tid + j * 256];
    }
    // stage x pairs: 6 pairs x 32 k-quads = 192 items
    if (tid < 192) {
        int p = tid >> 5, k4 = tid & 31;
        const float4* P4 = (const float4*)d_pooled;
        size_t col = (size_t)ks * (KQ / 4) + k4;
        float4 a = P4[((size_t)(b * NR + n0 + 2 * p))     * (F_IN / 4) + col];
        float4 c = P4[((size_t)(b * NR + n0 + 2 * p + 1)) * (F_IN / 4) + col];
        float4* dst = (float4*)&xp[p][k4 * 4];
        dst[0] = make_float4(a.x, c.x, a.y, c.y);
        dst[1] = make_float4(a.z, c.z, a.w, c.w);
    }
    __syncthreads();

    int o = tid & 63;
    int q = tid >> 6;                        // 0..3, covers 32 k
    unsigned long long acc[MT / 2] = {};     // packed (2p, 2p+1) accumulators
    #pragma unroll
    for (int k2 = 0; k2 < 32; k2 += 2) {
        int kk = q * 32 + k2;
        unsigned long long w0 = packww(Ws[kk][o]);
        unsigned long long w1 = packww(Ws[kk + 1][o]);
        #pragma unroll
        for (int p = 0; p < MT / 2; p++) {
            ulonglong2 x2 = *(const ulonglong2*)&xp[p][kk];  // k, k+1
            ffma2(acc[p], x2.x, w0);
            ffma2(acc[p], x2.y, w1);
        }
    }
    #pragma unroll
    for (int p = 0; p < MT / 2; p++) {
        part[q][2 * p][o]     = __uint_as_float((unsigned)acc[p]);
        part[q][2 * p + 1][o] = __uint_as_float((unsigned)(acc[p] >> 32));
    }
    __syncthreads();

    for (int i = tid; i < MT * OO; i += 256) {
        int nl = i >> 6, oo = i & 63;
        float g = part[0][nl][oo] + part[1][nl][oo]
                + part[2][nl][oo] + part[3][nl][oo];
        d_g16[ks][((size_t)(b * NR + n0 + nl)) * OO + oo] = g;
    }
}

// ---------------- K5: finalize BN1 affine + bias + BN2 + write ----------------
__global__ void k_final(const float* __restrict__ gamma1,
                        const float* __restrict__ beta1,
                        const float* __restrict__ bl1,
                        const float* __restrict__ gamma2,
                        const float* __restrict__ beta2,
                        float* __restrict__ out) {
    int n = blockIdx.x;
    int t = threadIdx.x;
    int b = t >> 6, o = t & 63;

    const float inv1 = 1.0f / (BB * F_IN);
    float mean1 = d_s1[n] * inv1;
    float var1 = d_s2[n] * inv1 - mean1 * mean1;
    float a1 = gamma1[n] * rsqrtf(var1 + EPSV);
    float c1 = beta1[n] - a1 * mean1;

    size_t gi = ((size_t)(b * NR + n)) * OO + o;
    float gsum = 0.f;
    #pragma unroll
    for (int ks = 0; ks < KS; ks++) gsum += d_g16[ks][gi];
    float y = a1 * gsum + c1 * d_Wsum[o] + bl1[o];

    __shared__ float rs[256], rq[256];
    rs[t] = y;
    rq[t] = y * y;
    __syncthreads();
    for (int st = 128; st > 0; st >>= 1) {
        if (t < st) { rs[t] += rs[t + st]; rq[t] += rq[t + st]; }
        __syncthreads();
    }
    float mean = rs[0] * (1.0f / 256.0f);
    float var = rq[0] * (1.0f / 256.0f) - mean * mean;
    out[gi] = (y - mean) * rsqrtf(var + EPSV) * gamma2[n] + beta2[n];
}

// ---------------- launch ----------------
extern "C" void kernel_launch(void* const* d_in, const int* in_sizes, int n_in,
                              void* d_out, int out_size) {
    const float* features = (const float*)d_in[0];
    const float* rois     = (const float*)d_in[1];
    const float* gamma1   = (const float*)d_in[2];
    const float* beta1    = (const float*)d_in[3];
    const float* W1       = (const float*)d_in[4];
    const float* bl1      = (const float*)d_in[5];
    const float* gamma2   = (const float*)d_in[6];
    const float* beta2    = (const float*)d_in[7];
    float* out = (float*)d_out;

    dim3 tgrid(HW / 32, CC / 32, BB);
    k_transpose<<<tgrid, dim3(32, 8)>>>(features);
    k_build4<<<NBUILD + OO, 128>>>(W1);
    k_roipool<<<BB * NR, 256>>>(rois);
    dim3 ggrid(BB * (NR / MT), KS);
    k_gemm<<<ggrid, 256>>>();
    k_final<<<NR, 256>>>(gamma1, beta1, bl1, gamma2, beta2, out);
}

// round 15
// speedup vs baseline: 1.0530x; 1.0381x over previous
#include <cuda_runtime.h>
#include <float.h>

#define BB 4
#define NR 180
#define CC 512
#define HH 48
#define WW 48
#define HW (HH*WW)
#define F_IN 2048
#define OO 64
#define EPSV 1e-5f
#define C4 (CC/4)          // 128 float4 per (h,w)
#define LVLSZ (BB*HH*WW*CC)
#define KS 8               // gemm k-split (v4 shape)
#define KQ (F_IN/KS)       // 256
#define NBUILD (BB*WW*(CC/128))   // 768 column-scan blocks

// ---------------- device scratch ----------------
__device__ float d_feat_t[LVLSZ];               // [B,H,W,C] level pw=1 (transposed)
__device__ float d_lvl[2 * LVLSZ];              // levels pw=4, pw=12
__device__ float d_pooled[BB * NR * F_IN];      // relu'd pooled
__device__ float d_W1t[F_IN * OO];              // W1 transposed [F,O]
__device__ float d_Wsum[OO];                    // sum_f W1[o,f]
__device__ float d_s1[NR];                      // per-n sum over (b,f)
__device__ float d_s2[NR];                      // per-n sumsq
__device__ float d_g[BB * NR * OO];             // GEMM accumulator (atomic)

__device__ __forceinline__ void max4(float4& a, const float4& b) {
    a.x = fmaxf(a.x, b.x); a.y = fmaxf(a.y, b.y);
    a.z = fmaxf(a.z, b.z); a.w = fmaxf(a.w, b.w);
}

// ---------------- K1: features [B,C,HW] -> [B,HW,C], tiled, coalesced ----------
__global__ void k_transpose(const float* __restrict__ feat) {
    __shared__ float tile[32][33];
    int b = blockIdx.z;
    int c0 = blockIdx.y * 32;
    int p0 = blockIdx.x * 32;       // HW=2304 divisible by 32
    #pragma unroll
    for (int k = 0; k < 32; k += 8) {
        int c = c0 + threadIdx.y + k;
        tile[threadIdx.y + k][threadIdx.x] =
            feat[((size_t)(b * CC + c)) * HW + p0 + threadIdx.x];
    }
    __syncthreads();
    #pragma unroll
    for (int k = 0; k < 32; k += 8) {
        int p = p0 + threadIdx.y + k;
        d_feat_t[((size_t)b * HW + p) * CC + c0 + threadIdx.x] =
            tile[threadIdx.x][threadIdx.y + k];
    }
}

// ---------------- K2: column-scan sparse-table build + W1 prep + zero d_g ------
__global__ void __launch_bounds__(128) k_build4(const float* __restrict__ W1) {
    int blk = blockIdx.x;
    int tid = threadIdx.x;

    if (blk >= NBUILD) {
        int o = blk - NBUILD;                   // 0..63
        if (o == 0) {
            for (int i = tid; i < NR; i += 128) { d_s1[i] = 0.f; d_s2[i] = 0.f; }
        }
        // zero this o's slice of d_g: 720 floats
        for (int i = tid; i < BB * NR; i += 128)
            d_g[(size_t)i * OO + o] = 0.f;
        __shared__ float red[128];
        float s = 0.f;
        for (int f = tid; f < F_IN; f += 128) {
            float v = W1[o * F_IN + f];
            d_W1t[f * OO + o] = v;
            s += v;
        }
        red[tid] = s;
        __syncthreads();
        for (int st = 64; st > 0; st >>= 1) {
            if (tid < st) red[tid] += red[tid + st];
            __syncthreads();
        }
        if (tid == 0) d_Wsum[o] = red[0];
        return;
    }

    int bw = blk >> 2;                  // (b,w)
    int cp = blk & 3;                   // channel part
    int b = bw / WW, w = bw % WW;
    int c = cp * 128 + tid;

    size_t base = ((size_t)(b * HH) * WW + w) * CC + c;
    const size_t HS = (size_t)WW * CC;  // h stride

    float v[HH];
    #pragma unroll
    for (int h = 0; h < HH; h++) v[h] = d_feat_t[base + h * HS];

    // pw1 -> pw4: passes d=1 then d=2
    #pragma unroll
    for (int h = 0; h < HH - 1; h++) v[h] = fmaxf(v[h], v[h + 1]);
    #pragma unroll
    for (int h = 0; h < HH - 2; h++) v[h] = fmaxf(v[h], v[h + 2]);
    #pragma unroll
    for (int h = 0; h < HH; h++) d_lvl[base + h * HS] = v[h];           // pw4

    // pw4 -> pw12: two d=4 passes
    #pragma unroll
    for (int h = 0; h < HH - 4; h++) v[h] = fmaxf(v[h], v[h + 4]);
    #pragma unroll
    for (int h = 0; h < HH - 8; h++) v[h] = fmaxf(v[h], v[h + 4]);
    #pragma unroll
    for (int h = 0; h < HH; h++) d_lvl[LVLSZ + base + h * HS] = v[h];   // pw12
}

// ---------------- K3: ROI pool via range-max lookups + ReLU + BN1 stats --------
__global__ void __launch_bounds__(256) k_roipool(const float* __restrict__ rois) {
    int bn = blockIdx.x;
    int b = bn / NR;
    const float* r = rois + bn * 4;
    int r0 = (int)truncf(r[0] * 0.25f), r1 = (int)truncf(r[1] * 0.25f);
    int r2 = (int)ceilf(r[2] * 0.25f),  r3 = (int)ceilf(r[3] * 0.25f);
    int hs = r2 - r0 + 1, ws = r3 - r1 + 1;
    int lenh = (hs + 1) >> 1;
    int lenw = (ws + 1) >> 1;
    int sh1 = r0 + (hs >> 1);
    int sw1 = r1 + (ws >> 1);

    const float* Lf;
    int pw;
    if (lenh >= 12)     { pw = 12; Lf = d_lvl + (size_t)LVLSZ; }
    else if (lenh >= 4) { pw = 4;  Lf = d_lvl; }
    else                { pw = 1;  Lf = d_feat_t; }
    int nlk = (lenh + pw - 1) / pw;       // 1..3
    const float4* L4 = (const float4*)Lf;

    int tid = threadIdx.x;
    int cq = tid & 127;
    int half = tid >> 7;
    int wstart = half ? sw1 : r1;
    size_t rb = (size_t)(b * HH) * WW;

    const float4 NEG = make_float4(-FLT_MAX, -FLT_MAX, -FLT_MAX, -FLT_MAX);
    float4 m0 = NEG, m1 = NEG;
    int cap = lenh - pw;
    for (int j = 0; j < nlk; j++) {
        int ho = j * pw; if (ho > cap) ho = cap;
        const float4* pA = L4 + (rb + (size_t)(r0  + ho) * WW + wstart) * C4 + cq;
        const float4* pB = L4 + (rb + (size_t)(sh1 + ho) * WW + wstart) * C4 + cq;
        #pragma unroll 2
        for (int w = lenw; w > 0; --w) {
            float4 va = *pA, vb = *pB;
            pA += C4; pB += C4;
            max4(m0, va); max4(m1, vb);
        }
    }

    __shared__ float4 sm0[128], sm1[128];
    __shared__ float rs[128], rq[128];
    if (half == 1) { sm0[cq] = m0; sm1[cq] = m1; }
    __syncthreads();
    if (half == 0) {
        const float4 Z = make_float4(0.f, 0.f, 0.f, 0.f);
        float4 m00 = m0, m10 = m1, m01 = sm0[cq], m11 = sm1[cq];
        max4(m00, Z); max4(m01, Z); max4(m10, Z); max4(m11, Z);
        float4 o0 = make_float4(m00.x, m01.x, m10.x, m11.x);
        float4 o1 = make_float4(m00.y, m01.y, m10.y, m11.y);
        float4 o2 = make_float4(m00.z, m01.z, m10.z, m11.z);
        float4 o3 = make_float4(m00.w, m01.w, m10.w, m11.w);
        float4* out = (float4*)(d_pooled + (size_t)bn * F_IN + cq * 16);
        out[0] = o0; out[1] = o1; out[2] = o2; out[3] = o3;
        float s = (o0.x + o0.y + o0.z + o0.w) + (o1.x + o1.y + o1.z + o1.w)
                + (o2.x + o2.y + o2.z + o2.w) + (o3.x + o3.y + o3.z + o3.w);
        float q = o0.x*o0.x + o0.y*o0.y + o0.z*o0.z + o0.w*o0.w
                + o1.x*o1.x + o1.y*o1.y + o1.z*o1.z + o1.w*o1.w
                + o2.x*o2.x + o2.y*o2.y + o2.z*o2.z + o2.w*o2.w
                + o3.x*o3.x + o3.y*o3.y + o3.z*o3.z + o3.w*o3.w;
        rs[cq] = s; rq[cq] = q;
    }
    __syncthreads();
    for (int st = 64; st > 0; st >>= 1) {
        if (tid < st) { rs[tid] += rs[tid + st]; rq[tid] += rq[tid + st]; }
        __syncthreads();
    }
    if (tid == 0) {
        int n = bn % NR;
        atomicAdd(&d_s1[n], rs[0]);
        atomicAdd(&d_s2[n], rq[0]);
    }
}

// ---------------- K4: GEMM (v4 compute, atomic epilogue) ------------------------
// grid (180, 8), 256 threads = 32 o-pairs x 8 q-groups(32k each).
__global__ void __launch_bounds__(256) k_gemm() {
    __shared__ float xs[4][KQ];              // 4KB
    __shared__ float part[8][4][OO];         // 8KB
    int mb = blockIdx.x;                     // 0..179
    int ks = blockIdx.y;                     // 0..7
    int b = mb / (NR / 4);
    int n0 = (mb % (NR / 4)) * 4;
    int tid = threadIdx.x;

    // load xs: 4 ROIs x 256 k = 256 float4, one per thread
    {
        int nl = tid >> 6, k4 = tid & 63;
        const float4* P4 = (const float4*)d_pooled;
        float4 v = P4[((size_t)(b * NR + n0 + nl)) * (F_IN / 4) + ks * (KQ / 4) + k4];
        *(float4*)&xs[nl][k4 * 4] = v;
    }
    __syncthreads();

    int o2 = (tid & 31) * 2;
    int q = tid >> 5;                        // 0..7, covers 32 k
    float acc[4][2] = {};
    const float* Wp = d_W1t + (size_t)(ks * KQ + q * 32) * OO;
    #pragma unroll 2
    for (int k = 0; k < 32; k += 4) {
        float2 w0 = *(const float2*)&Wp[(k + 0) * OO + o2];
        float2 w1 = *(const float2*)&Wp[(k + 1) * OO + o2];
        float2 w2 = *(const float2*)&Wp[(k + 2) * OO + o2];
        float2 w3 = *(const float2*)&Wp[(k + 3) * OO + o2];
        #pragma unroll
        for (int nl = 0; nl < 4; nl++) {
            float4 x = *(const float4*)&xs[nl][q * 32 + k];
            acc[nl][0] = fmaf(x.x, w0.x, acc[nl][0]);
            acc[nl][1] = fmaf(x.x, w0.y, acc[nl][1]);
            acc[nl][0] = fmaf(x.y, w1.x, acc[nl][0]);
            acc[nl][1] = fmaf(x.y, w1.y, acc[nl][1]);
            acc[nl][0] = fmaf(x.z, w2.x, acc[nl][0]);
            acc[nl][1] = fmaf(x.z, w2.y, acc[nl][1]);
            acc[nl][0] = fmaf(x.w, w3.x, acc[nl][0]);
            acc[nl][1] = fmaf(x.w, w3.y, acc[nl][1]);
        }
    }
    #pragma unroll
    for (int nl = 0; nl < 4; nl++) {
        part[q][nl][o2] = acc[nl][0];
        part[q][nl][o2 + 1] = acc[nl][1];
    }
    __syncthreads();

    // one output per thread: reduce 8 q-groups, atomic-accumulate k-slices
    {
        int nl = tid >> 6, o = tid & 63;
        float g = 0.f;
        #pragma unroll
        for (int qq = 0; qq < 8; qq++) g += part[qq][nl][o];
        atomicAdd(&d_g[((size_t)(b * NR + n0 + nl)) * OO + o], g);
    }
}

// ---------------- K5: finalize BN1 affine + bias + BN2 + write ----------------
__global__ void k_final(const float* __restrict__ gamma1,
                        const float* __restrict__ beta1,
                        const float* __restrict__ bl1,
                        const float* __restrict__ gamma2,
                        const float* __restrict__ beta2,
                        float* __restrict__ out) {
    int n = blockIdx.x;
    int t = threadIdx.x;
    int b = t >> 6, o = t & 63;

    const float inv1 = 1.0f / (BB * F_IN);
    float mean1 = d_s1[n] * inv1;
    float var1 = d_s2[n] * inv1 - mean1 * mean1;
    float a1 = gamma1[n] * rsqrtf(var1 + EPSV);
    float c1 = beta1[n] - a1 * mean1;

    size_t gi = ((size_t)(b * NR + n)) * OO + o;
    float y = a1 * d_g[gi] + c1 * d_Wsum[o] + bl1[o];

    __shared__ float rs[256], rq[256];
    rs[t] = y;
    rq[t] = y * y;
    __syncthreads();
    for (int st = 128; st > 0; st >>= 1) {
        if (t < st) { rs[t] += rs[t + st]; rq[t] += rq[t + st]; }
        __syncthreads();
    }
    float mean = rs[0] * (1.0f / 256.0f);
    float var = rq[0] * (1.0f / 256.0f) - mean * mean;
    out[gi] = (y - mean) * rsqrtf(var + EPSV) * gamma2[n] + beta2[n];
}

// ---------------- launch ----------------
extern "C" void kernel_launch(void* const* d_in, const int* in_sizes, int n_in,
                              void* d_out, int out_size) {
    const float* features = (const float*)d_in[0];
    const float* rois     = (const float*)d_in[1];
    const float* gamma1   = (const float*)d_in[2];
    const float* beta1    = (const float*)d_in[3];
    const float* W1       = (const float*)d_in[4];
    const float* bl1      = (const float*)d_in[5];
    const float* gamma2   = (const float*)d_in[6];
    const float* beta2    = (const float*)d_in[7];
    float* out = (float*)d_out;

    dim3 tgrid(HW / 32, CC / 32, BB);
    k_transpose<<<tgrid, dim3(32, 8)>>>(features);
    k_build4<<<NBUILD + OO, 128>>>(W1);
    k_roipool<<<BB * NR, 256>>>(rois);
    dim3 ggrid(BB * (NR / 4), KS);
    k_gemm<<<ggrid, 256>>>();
    k_final<<<NR, 256>>>(gamma1, beta1, bl1, gamma2, beta2, out);
}

// round 16
// speedup vs baseline: 1.2059x; 1.1452x over previous
#include <cuda_runtime.h>
#include <float.h>

#define BB 4
#define NR 180
#define CC 512
#define HH 48
#define WW 48
#define HW (HH*WW)
#define F_IN 2048
#define OO 64
#define EPSV 1e-5f
#define C4 (CC/4)          // 128 float4 per (h,w)
#define LVLSZ (BB*HH*WW*CC)
#define KS 8               // gemm k-split
#define KQ (F_IN/KS)       // 256
#define HSTR 288           // smem h-stride (floats): w*36 + c, conflict-engineered
#define NPREP (16*6*BB)    // 384 prep blocks (c-tiles x w-tiles x b)

// ---------------- device scratch ----------------
__device__ float d_feat_t[LVLSZ];               // [B,H,W,C] level pw=1 (transposed)
__device__ float d_lvl[2 * LVLSZ];              // levels pw=4, pw=12
__device__ float d_pooled[BB * NR * F_IN];      // relu'd pooled
__device__ float d_W1t[F_IN * OO];              // W1 transposed [F,O]
__device__ float d_Wsum[OO];                    // sum_f W1[o,f]
__device__ float d_s1[NR];                      // per-n sum over (b,f)
__device__ float d_s2[NR];                      // per-n sumsq
__device__ float d_g[BB * NR * OO];             // GEMM accumulator (atomic)

__device__ __forceinline__ void max4(float4& a, const float4& b) {
    a.x = fmaxf(a.x, b.x); a.y = fmaxf(a.y, b.y);
    a.z = fmaxf(a.z, b.z); a.w = fmaxf(a.w, b.w);
}

// ---------------- K1: fused transpose + h sparse-table build + W1 prep ----------
// blocks 0..383: one (32c x 8w x 48h) tile; blocks 384..447: W1 prep + zeroing.
__global__ void __launch_bounds__(256) k_prep(const float* __restrict__ feat,
                                              const float* __restrict__ W1) {
    int blk = blockIdx.x;
    int tid = threadIdx.x;

    if (blk >= NPREP) {
        // ---- W1 prep path ----
        int o = blk - NPREP;                    // 0..63
        if (o == 0) {
            for (int i = tid; i < NR; i += 256) { d_s1[i] = 0.f; d_s2[i] = 0.f; }
        }
        for (int i = tid; i < BB * NR; i += 256)
            d_g[(size_t)i * OO + o] = 0.f;
        __shared__ float red[256];
        float s = 0.f;
        for (int f = tid; f < F_IN; f += 256) {
            float v = W1[o * F_IN + f];
            d_W1t[f * OO + o] = v;
            s += v;
        }
        red[tid] = s;
        __syncthreads();
        for (int st = 128; st > 0; st >>= 1) {
            if (tid < st) red[tid] += red[tid + st];
            __syncthreads();
        }
        if (tid == 0) d_Wsum[o] = red[0];
        return;
    }

    // ---- prep path ----
    extern __shared__ float ts[];               // 48 * HSTR floats = 55296 B
    int cg = blk & 15;
    int wg = (blk >> 4) % 6;
    int b = blk / 96;
    int c0 = cg * 32, w0 = wg * 8;

    // Phase A: load gmem -> smem. mapping (c=tid>>3, w=tid&7); 4x32B sectors/warp.
    {
        int ca = tid >> 3, wa = tid & 7;
        const float* src = feat + ((size_t)(b * CC + c0 + ca)) * HW + w0 + wa;
        float* d = ts + wa * 36 + ca;
        #pragma unroll
        for (int h = 0; h < HH; h++)
            d[h * HSTR] = src[h * WW];
    }
    __syncthreads();

    // store_level: smem -> gmem [p][C], 128B-coalesced float4 stores
    float* const base0 = d_feat_t + (size_t)b * HW * CC + (size_t)w0 * CC + c0;
    float* const base1 = d_lvl    + (size_t)b * HW * CC + (size_t)w0 * CC + c0;
    float* const base2 = d_lvl + LVLSZ + (size_t)b * HW * CC + (size_t)w0 * CC + c0;
    auto store_level = [&](float* dst) {
        #pragma unroll
        for (int j = 0; j < 12; j++) {
            int i4 = tid + j * 256;             // 0..3071
            int c4 = i4 & 7, w8 = (i4 >> 3) & 7, h = i4 >> 6;
            float4 val = *(const float4*)&ts[h * HSTR + w8 * 36 + c4 * 4];
            *(float4*)&dst[((size_t)h * WW + w8) * CC + c4 * 4] = val;
        }
    };

    // Phase B: register column scan. mapping (c=tid&31, w=tid>>5); all cf.
    int cb = tid & 31, wb = tid >> 5;
    float* col = ts + wb * 36 + cb;
    float v[HH];
    #pragma unroll
    for (int h = 0; h < HH; h++) v[h] = col[h * HSTR];

    store_level(base0);                          // pw1

    // pw1 -> pw4 in regs: passes d=1 then d=2
    #pragma unroll
    for (int h = 0; h < HH - 1; h++) v[h] = fmaxf(v[h], v[h + 1]);
    #pragma unroll
    for (int h = 0; h < HH - 2; h++) v[h] = fmaxf(v[h], v[h + 2]);
    __syncthreads();                             // all pw1 reads done
    #pragma unroll
    for (int h = 0; h < HH; h++) col[h * HSTR] = v[h];
    __syncthreads();
    store_level(base1);                          // pw4

    // pw4 -> pw12 in regs: two d=4 passes
    #pragma unroll
    for (int h = 0; h < HH - 4; h++) v[h] = fmaxf(v[h], v[h + 4]);
    #pragma unroll
    for (int h = 0; h < HH - 8; h++) v[h] = fmaxf(v[h], v[h + 4]);
    __syncthreads();                             // all pw4 reads done
    #pragma unroll
    for (int h = 0; h < HH; h++) col[h * HSTR] = v[h];
    __syncthreads();
    store_level(base2);                          // pw12
}

// ---------------- K2: ROI pool via range-max lookups + ReLU + BN1 stats --------
__global__ void __launch_bounds__(256) k_roipool(const float* __restrict__ rois) {
    int bn = blockIdx.x;
    int b = bn / NR;
    const float* r = rois + bn * 4;
    int r0 = (int)truncf(r[0] * 0.25f), r1 = (int)truncf(r[1] * 0.25f);
    int r2 = (int)ceilf(r[2] * 0.25f),  r3 = (int)ceilf(r[3] * 0.25f);
    int hs = r2 - r0 + 1, ws = r3 - r1 + 1;
    int lenh = (hs + 1) >> 1;
    int lenw = (ws + 1) >> 1;
    int sh1 = r0 + (hs >> 1);
    int sw1 = r1 + (ws >> 1);

    const float* Lf;
    int pw;
    if (lenh >= 12)     { pw = 12; Lf = d_lvl + (size_t)LVLSZ; }
    else if (lenh >= 4) { pw = 4;  Lf = d_lvl; }
    else                { pw = 1;  Lf = d_feat_t; }
    int nlk = (lenh + pw - 1) / pw;       // 1..3
    const float4* L4 = (const float4*)Lf;

    int tid = threadIdx.x;
    int cq = tid & 127;
    int half = tid >> 7;
    int wstart = half ? sw1 : r1;
    size_t rb = (size_t)(b * HH) * WW;

    const float4 NEG = make_float4(-FLT_MAX, -FLT_MAX, -FLT_MAX, -FLT_MAX);
    float4 m0 = NEG, m1 = NEG;
    int cap = lenh - pw;
    for (int j = 0; j < nlk; j++) {
        int ho = j * pw; if (ho > cap) ho = cap;
        const float4* pA = L4 + (rb + (size_t)(r0  + ho) * WW + wstart) * C4 + cq;
        const float4* pB = L4 + (rb + (size_t)(sh1 + ho) * WW + wstart) * C4 + cq;
        #pragma unroll 2
        for (int w = lenw; w > 0; --w) {
            float4 va = *pA, vb = *pB;
            pA += C4; pB += C4;
            max4(m0, va); max4(m1, vb);
        }
    }

    __shared__ float4 sm0[128], sm1[128];
    __shared__ float rs[128], rq[128];
    if (half == 1) { sm0[cq] = m0; sm1[cq] = m1; }
    __syncthreads();
    if (half == 0) {
        const float4 Z = make_float4(0.f, 0.f, 0.f, 0.f);
        float4 m00 = m0, m10 = m1, m01 = sm0[cq], m11 = sm1[cq];
        max4(m00, Z); max4(m01, Z); max4(m10, Z); max4(m11, Z);
        float4 o0 = make_float4(m00.x, m01.x, m10.x, m11.x);
        float4 o1 = make_float4(m00.y, m01.y, m10.y, m11.y);
        float4 o2 = make_float4(m00.z, m01.z, m10.z, m11.z);
        float4 o3 = make_float4(m00.w, m01.w, m10.w, m11.w);
        float4* out = (float4*)(d_pooled + (size_t)bn * F_IN + cq * 16);
        out[0] = o0; out[1] = o1; out[2] = o2; out[3] = o3;
        float s = (o0.x + o0.y + o0.z + o0.w) + (o1.x + o1.y + o1.z + o1.w)
                + (o2.x + o2.y + o2.z + o2.w) + (o3.x + o3.y + o3.z + o3.w);
        float q = o0.x*o0.x + o0.y*o0.y + o0.z*o0.z + o0.w*o0.w
                + o1.x*o1.x + o1.y*o1.y + o1.z*o1.z + o1.w*o1.w
                + o2.x*o2.x + o2.y*o2.y + o2.z*o2.z + o2.w*o2.w
                + o3.x*o3.x + o3.y*o3.y + o3.z*o3.z + o3.w*o3.w;
        rs[cq] = s; rq[cq] = q;
    }
    __syncthreads();
    for (int st = 64; st > 0; st >>= 1) {
        if (tid < st) { rs[tid] += rs[tid + st]; rq[tid] += rq[tid + st]; }
        __syncthreads();
    }
    if (tid == 0) {
        int n = bn % NR;
        atomicAdd(&d_s1[n], rs[0]);
        atomicAdd(&d_s2[n], rq[0]);
    }
}

// ---------------- K3: GEMM (v4 compute, atomic epilogue) ------------------------
__global__ void __launch_bounds__(256) k_gemm() {
    __shared__ float xs[4][KQ];              // 4KB
    __shared__ float part[8][4][OO];         // 8KB
    int mb = blockIdx.x;                     // 0..179
    int ks = blockIdx.y;                     // 0..7
    int b = mb / (NR / 4);
    int n0 = (mb % (NR / 4)) * 4;
    int tid = threadIdx.x;

    {
        int nl = tid >> 6, k4 = tid & 63;
        const float4* P4 = (const float4*)d_pooled;
        float4 v = P4[((size_t)(b * NR + n0 + nl)) * (F_IN / 4) + ks * (KQ / 4) + k4];
        *(float4*)&xs[nl][k4 * 4] = v;
    }
    __syncthreads();

    int o2 = (tid & 31) * 2;
    int q = tid >> 5;                        // 0..7, covers 32 k
    float acc[4][2] = {};
    const float* Wp = d_W1t + (size_t)(ks * KQ + q * 32) * OO;
    #pragma unroll 2
    for (int k = 0; k < 32; k += 4) {
        float2 w0 = *(const float2*)&Wp[(k + 0) * OO + o2];
        float2 w1 = *(const float2*)&Wp[(k + 1) * OO + o2];
        float2 w2 = *(const float2*)&Wp[(k + 2) * OO + o2];
        float2 w3 = *(const float2*)&Wp[(k + 3) * OO + o2];
        #pragma unroll
        for (int nl = 0; nl < 4; nl++) {
            float4 x = *(const float4*)&xs[nl][q * 32 + k];
            acc[nl][0] = fmaf(x.x, w0.x, acc[nl][0]);
            acc[nl][1] = fmaf(x.x, w0.y, acc[nl][1]);
            acc[nl][0] = fmaf(x.y, w1.x, acc[nl][0]);
            acc[nl][1] = fmaf(x.y, w1.y, acc[nl][1]);
            acc[nl][0] = fmaf(x.z, w2.x, acc[nl][0]);
            acc[nl][1] = fmaf(x.z, w2.y, acc[nl][1]);
            acc[nl][0] = fmaf(x.w, w3.x, acc[nl][0]);
            acc[nl][1] = fmaf(x.w, w3.y, acc[nl][1]);
        }
    }
    #pragma unroll
    for (int nl = 0; nl < 4; nl++) {
        part[q][nl][o2] = acc[nl][0];
        part[q][nl][o2 + 1] = acc[nl][1];
    }
    __syncthreads();

    {
        int nl = tid >> 6, o = tid & 63;
        float g = 0.f;
        #pragma unroll
        for (int qq = 0; qq < 8; qq++) g += part[qq][nl][o];
        atomicAdd(&d_g[((size_t)(b * NR + n0 + nl)) * OO + o], g);
    }
}

// ---------------- K4: finalize BN1 affine + bias + BN2 + write ----------------
__global__ void k_final(const float* __restrict__ gamma1,
                        const float* __restrict__ beta1,
                        const float* __restrict__ bl1,
                        const float* __restrict__ gamma2,
                        const float* __restrict__ beta2,
                        float* __restrict__ out) {
    int n = blockIdx.x;
    int t = threadIdx.x;
    int b = t >> 6, o = t & 63;

    const float inv1 = 1.0f / (BB * F_IN);
    float mean1 = d_s1[n] * inv1;
    float var1 = d_s2[n] * inv1 - mean1 * mean1;
    float a1 = gamma1[n] * rsqrtf(var1 + EPSV);
    float c1 = beta1[n] - a1 * mean1;

    size_t gi = ((size_t)(b * NR + n)) * OO + o;
    float y = a1 * d_g[gi] + c1 * d_Wsum[o] + bl1[o];

    __shared__ float rs[256], rq[256];
    rs[t] = y;
    rq[t] = y * y;
    __syncthreads();
    for (int st = 128; st > 0; st >>= 1) {
        if (t < st) { rs[t] += rs[t + st]; rq[t] += rq[t + st]; }
        __syncthreads();
    }
    float mean = rs[0] * (1.0f / 256.0f);
    float var = rq[0] * (1.0f / 256.0f) - mean * mean;
    out[gi] = (y - mean) * rsqrtf(var + EPSV) * gamma2[n] + beta2[n];
}

// ---------------- launch ----------------
extern "C" void kernel_launch(void* const* d_in, const int* in_sizes, int n_in,
                              void* d_out, int out_size) {
    const float* features = (const float*)d_in[0];
    const float* rois     = (const float*)d_in[1];
    const float* gamma1   = (const float*)d_in[2];
    const float* beta1    = (const float*)d_in[3];
    const float* W1       = (const float*)d_in[4];
    const float* bl1      = (const float*)d_in[5];
    const float* gamma2   = (const float*)d_in[6];
    const float* beta2    = (const float*)d_in[7];
    float* out = (float*)d_out;

    static bool attr_done = false;
    const int PREP_SMEM = HH * HSTR * 4;     // 55296 B
    if (!attr_done) {
        cudaFuncSetAttribute(k_prep, cudaFuncAttributeMaxDynamicSharedMemorySize, PREP_SMEM);
        attr_done = true;
    }

    k_prep<<<NPREP + OO, 256, PREP_SMEM>>>(features, W1);
    k_roipool<<<BB * NR, 256>>>(rois);
    dim3 ggrid(BB * (NR / 4), KS);
    k_gemm<<<ggrid, 256>>>();
    k_final<<<NR, 256>>>(gamma1, beta1, bl1, gamma2, beta2, out);
}